// round 3
// baseline (speedup 1.0000x reference)
#include <cuda_runtime.h>

// KalmanFilter: B=128, T=256, V=256. Exact decoupling into two 2-state
// (pos,vel) filters sharing one symmetric 2x2 covariance (a,b,c) whose
// recursion depends only on the per-step mask.
//
// Memory engine: cp.async 5-stage smem ring, refill issued BEFORE consume.

#define TQ 256
#define VQ 256
#define FSTEP (VQ * 3)            // floats per timestep per batch elem: 768
#define DCH 16                    // timesteps per chunk
#define NCH (TQ / DCH)            // 16 chunks
#define STAGES 5
#define TPB 32                    // one warp per block
#define TRACKS 32
#define FLT_PER_STEP (TRACKS * 3)         // 96 floats per step per block
#define F4_PER_STEP  (FLT_PER_STEP / 4)   // 24 float4
#define F4_PER_CHUNK (DCH * F4_PER_STEP)  // 384 float4 = 6144 B
#define F4_PER_THR   (F4_PER_CHUNK / TPB) // 12 cp.async per thread per chunk

__global__ void __launch_bounds__(TPB)
kalman_kernel(const float* __restrict__ batch, float* __restrict__ out)
{
    __shared__ float4 buf[STAGES][F4_PER_CHUNK];   // 5 * 6 KB = 30 KB

    const int tid = threadIdx.x;
    const int b   = blockIdx.x >> 3;               // 8 blocks per batch elem
    const int v0  = (blockIdx.x & 7) * TRACKS;
    const char* gbase = (const char*)(batch + ((size_t)b * TQ * VQ + v0) * 3);

    auto issue = [&](int chunk, int s) {
        const char* cbase = gbase + (size_t)chunk * DCH * (FSTEP * 4);
        unsigned sbase = (unsigned)__cvta_generic_to_shared(&buf[s][0]);
        #pragma unroll
        for (int k = 0; k < F4_PER_THR; k++) {
            int j    = tid + k * TPB;
            int step = j / F4_PER_STEP;
            int rem  = j - step * F4_PER_STEP;
            const char* g = cbase + step * (FSTEP * 4) + rem * 16;
            unsigned sa   = sbase + (unsigned)j * 16;
            asm volatile("cp.async.cg.shared.global [%0], [%1], 16;\n"
                         :: "r"(sa), "l"(g));
        }
        asm volatile("cp.async.commit_group;\n" ::: "memory");
    };

    // ---- filter state ----
    // (a,b,c) = predicted covariance P_pred for the upcoming step.
    // P0 = 1000 I  =>  first P_pred = F P0 F^T + Q = [[2000.01,1000],[1000,1000.01]]
    float a = 2000.01f, bb = 1000.0f, cc = 1000.01f;
    // (sx0,sx1)/(sy0,sy1) = updated state after previous step (s0 = 0).
    float sx0 = 0.f, sx1 = 0.f, sy0 = 0.f, sy1 = 0.f;

    auto kstep = [&](float lab, float zx, float zy) {
        bool  msk = (lab != -1.0f);
        float inv = __fdividef(1.0f, a + 1.0f);
        float m   = msk ? inv : 1.0f;      // (1 - k0) exactly
        float g   = msk ? inv : 0.0f;
        // state: predict then correct
        float sxp = sx0 + sx1;
        float syp = sy0 + sy1;
        float k0  = a * g;
        float k1  = bb * g;
        float rx  = zx - sxp;
        float ry  = zy - syp;
        sx0 = fmaf(k0, rx, sxp);
        sx1 = fmaf(k1, rx, sx1);
        sy0 = fmaf(k0, ry, syp);
        sy1 = fmaf(k1, ry, sy1);
        // covariance: update then predict
        float u00 = a * m;
        float u01 = bb * m;
        float u11 = fmaf(-g * bb, bb, cc);
        a   = fmaf(2.0f, u01, u00) + (u11 + 0.01f);
        bb  = u01 + u11;
        cc  = u11 + 0.01f;
    };

    // ---- prologue: fill 4 of 5 stages ----
    issue(0, 0);
    issue(1, 1);
    issue(2, 2);
    issue(3, 3);

    #pragma unroll 1
    for (int c = 0; c < NCH; c++) {
        // refill FIRST: stage (c+4)%5 == (c-1)%5 was consumed last iteration
        if (c + 4 < NCH) issue(c + 4, (c + 4) % STAGES);
        // chunk c must be complete (<= 4 newer groups outstanding)
        asm volatile("cp.async.wait_group 4;\n" ::: "memory");
        __syncwarp();

        const float* sb = (const float*)&buf[c % STAGES][0];
        #pragma unroll
        for (int i = 0; i < DCH; i++) {
            float lab = sb[i * FLT_PER_STEP + tid * 3 + 0];
            float zx  = sb[i * FLT_PER_STEP + tid * 3 + 1];
            float zy  = sb[i * FLT_PER_STEP + tid * 3 + 2];
            kstep(lab, zx, zy);
        }
        __syncwarp();
    }

    float* o = out + ((size_t)b * VQ + v0 + tid) * 3;
    o[0] = 1.0f;
    o[1] = sx0;
    o[2] = sy0;
}

extern "C" void kernel_launch(void* const* d_in, const int* in_sizes, int n_in,
                              void* d_out, int out_size)
{
    const float* batch = (const float*)d_in[0];
    float* out = (float*)d_out;
    kalman_kernel<<<1024, TPB>>>(batch, out);
}